// round 4
// baseline (speedup 1.0000x reference)
#include <cuda_runtime.h>

// Flow1: K=32, B=4096, ZS=128, ZH=64, HS=50, NF=2
#define KK   32
#define BB   4096
#define ZSv  128
#define ZHv  64
#define HSv  50
#define HSP  52                 // HS padded to multiple of 4 (zero-padded)
#define ROWS (KK*BB)            // 131072
#define TPB  128
#define NBLK (ROWS/TPB)         // 1024 CTAs, 1 row per thread
#define SSTR 129                // staging row stride (conflict-free scalar)

// smem: union region (weights 10164 floats  >=  stage 64*129=8256) + rowpart 512
#define WREG  (HSP*ZHv + 2*ZHv*HSP + HSP + 2*ZHv)   // 10164
#define SMEM_FLOATS (WREG + TPB*4)
#define SMEM_BYTES  (SMEM_FLOATS * 4)               // ~42.7 KB -> 2 CTAs (reg-limited)

__device__ __forceinline__ float fast_tanh(float x) {
    float e = __expf(-2.f * fabsf(x));
    float t = __fdividef(1.f - e, 1.f + e);
    return copysignf(t, x);
}

// One coupling half-step: h = tanh(W0.zsrc + b0); ztgt = ztgt*sig + mew.
// Returns sum of log2(1 + exp(-sr)) over the 64 outputs.
__device__ __forceinline__ float half_step(
    float (&zsrc)[64], float (&ztgt)[64],
    const float* __restrict__ w0sh, const float* __restrict__ w1sh,
    const float* __restrict__ w2sh, const float* __restrict__ b0sh,
    const float* __restrict__ b1sh, const float* __restrict__ b2sh)
{
    float h[HSP];
    #pragma unroll
    for (int j = 0; j < HSP; j++) {
        float a0 = b0sh[j], a1 = 0.f;
        const float4* wr = reinterpret_cast<const float4*>(w0sh + j*ZHv);
        #pragma unroll
        for (int kq = 0; kq < 16; kq++) {
            float4 w = wr[kq];
            a0 = fmaf(w.x, zsrc[4*kq+0], a0);
            a0 = fmaf(w.y, zsrc[4*kq+1], a0);
            a1 = fmaf(w.z, zsrc[4*kq+2], a1);
            a1 = fmaf(w.w, zsrc[4*kq+3], a1);
        }
        h[j] = fast_tanh(a0 + a1);
    }

    float lg = 0.f;
    #pragma unroll
    for (int l = 0; l < ZHv; l++) {
        const float4* w1r = reinterpret_cast<const float4*>(w1sh + l*HSP);
        const float4* w2r = reinterpret_cast<const float4*>(w2sh + l*HSP);
        float m0 = b1sh[l], m1 = 0.f, s0 = b2sh[l], s1 = 0.f;
        #pragma unroll
        for (int p = 0; p < 13; p++) {
            float4 w1 = w1r[p];
            float4 w2 = w2r[p];
            m0 = fmaf(w1.x, h[4*p+0], m0);
            m0 = fmaf(w1.y, h[4*p+1], m0);
            m1 = fmaf(w1.z, h[4*p+2], m1);
            m1 = fmaf(w1.w, h[4*p+3], m1);
            s0 = fmaf(w2.x, h[4*p+0], s0);
            s0 = fmaf(w2.y, h[4*p+1], s0);
            s1 = fmaf(w2.z, h[4*p+2], s1);
            s1 = fmaf(w2.w, h[4*p+3], s1);
        }
        float mew = m0 + m1;
        float sr  = s0 + s1;
        float e   = __expf(-sr);
        float opr = 1.f + e;
        float g   = __fdividef(1.f, opr);
        lg += __log2f(opr);
        ztgt[l] = fmaf(ztgt[l], g, mew);
    }
    return lg;
}

__global__ void __launch_bounds__(TPB, 2) flow_kernel(
    const float* __restrict__ mean, const float* __restrict__ logvar,
    const float* __restrict__ eps,
    const float* __restrict__ W0, const float* __restrict__ b0,
    const float* __restrict__ W1, const float* __restrict__ b1,
    const float* __restrict__ W2, const float* __restrict__ b2,
    float* __restrict__ out)
{
    extern __shared__ float sm[];
    // union: weight buffers (main loop) overlap staging area (pro/epilogue)
    float* w0sh  = sm;                     // [HSP][ZHv]
    float* w1sh  = w0sh + HSP*ZHv;         // [ZHv][HSP]
    float* w2sh  = w1sh + ZHv*HSP;         // [ZHv][HSP]
    float* b0sh  = w2sh + ZHv*HSP;         // [HSP]
    float* b1sh  = b0sh + HSP;             // [ZHv]
    float* b2sh  = b1sh + ZHv;             // [ZHv]
    float* stage = sm;                     // [64][SSTR] (overlaps weights)
    float* rowpart = sm + WREG;            // [TPB][4] (persists whole kernel)

    const int tid  = threadIdx.x;
    const int lane = tid & 31;
    const int warp = tid >> 5;
    const size_t r0    = (size_t)blockIdx.x * TPB;
    const size_t bbase = (size_t)(r0 & (BB-1)) * ZSv;

    float z1[64], z2[64];

    // ---------------- prologue: z = eps*exp(0.5*lv)+mean ; rowsum(lv+eps^2) ----
    // two batches of 64 rows staged through smem -> owning thread's registers
    #pragma unroll 1
    for (int b = 0; b < 2; b++) {
        #pragma unroll 4
        for (int it = 0; it < 64; it++) {
            int row = b*64 + it;                          // CTA-local row
            size_t go = (size_t)row * ZSv + tid;          // col = tid
            float ep = eps[r0*ZSv + go];
            float lv = logvar[bbase + go];
            float mn = mean[bbase + go];
            stage[it*SSTR + tid] = fmaf(ep, __expf(0.5f*lv), mn);
            float c = fmaf(ep, ep, lv);
            #pragma unroll
            for (int o = 16; o; o >>= 1) c += __shfl_xor_sync(0xFFFFFFFFu, c, o);
            if (lane == 0) rowpart[row*4 + warp] = c;
        }
        __syncthreads();
        if ((tid >> 6) == b) {
            const float* srow = stage + (tid & 63) * SSTR;
            #pragma unroll
            for (int c = 0; c < 64; c++) { z1[c] = srow[c]; z2[c] = srow[64 + c]; }
        }
        __syncthreads();
    }

    float lg = 0.f;    // sum log2(1 + e^{-sr}); logdet = -ln2 * lg

    // ---------------- 4 flow half-steps (all z in registers) -------------------
    #pragma unroll 1
    for (int s = 0; s < 4; s++) {
        {   // stage this half-step's weights (zero-padded); overwrites stage area
            const float* W0g = W0 + s*(HSv*ZHv);
            #pragma unroll 1
            for (int i = tid; i < HSP*ZHv; i += TPB)
                w0sh[i] = (i < HSv*ZHv) ? W0g[i] : 0.f;
            const float* W1g = W1 + s*(ZHv*HSv);
            const float* W2g = W2 + s*(ZHv*HSv);
            #pragma unroll 1
            for (int i = tid; i < ZHv*HSP; i += TPB) {
                int l = i / HSP;
                int j = i - l*HSP;
                float v1 = 0.f, v2 = 0.f;
                if (j < HSv) { v1 = W1g[l*HSv + j]; v2 = W2g[l*HSv + j]; }
                w1sh[i] = v1;  w2sh[i] = v2;
            }
            if (tid < HSP) b0sh[tid] = (tid < HSv) ? b0[s*HSv + tid] : 0.f;
            if (tid < ZHv) { b1sh[tid] = b1[s*ZHv + tid]; b2sh[tid] = b2[s*ZHv + tid]; }
        }
        __syncthreads();

        if ((s & 1) == 0)
            lg += half_step(z1, z2, w0sh, w1sh, w2sh, b0sh, b1sh, b2sh);
        else
            lg += half_step(z2, z1, w0sh, w1sh, w2sh, b0sh, b1sh, b2sh);

        __syncthreads();   // all reads of this step's weights done before restage
    }

    // ---------------- epilogue: z_out (staged, coalesced), then logpz ----------
    #pragma unroll 1
    for (int b = 0; b < 2; b++) {
        if ((tid >> 6) == b) {
            float* srow = stage + (tid & 63) * SSTR;
            #pragma unroll
            for (int c = 0; c < 64; c++) { srow[c] = z1[c]; srow[64 + c] = z2[c]; }
        }
        __syncthreads();
        #pragma unroll 4
        for (int it = 0; it < 64; it++)
            out[(r0 + b*64 + it)*ZSv + tid] = stage[it*SSTR + tid];
        __syncthreads();
    }

    float rs = rowpart[tid*4+0] + rowpart[tid*4+1] + rowpart[tid*4+2] + rowpart[tid*4+3];
    float logq = -0.5f * ((float)ZSv * 1.8378770664093453f + rs);   // ln(2*pi)
    // logpz = logq - logdet = logq + ln2 * lg
    out[(size_t)ROWS*ZSv + r0 + tid] = logq + 0.69314718055994531f * lg;
}

extern "C" void kernel_launch(void* const* d_in, const int* in_sizes, int n_in,
                              void* d_out, int out_size) {
    (void)in_sizes; (void)n_in; (void)out_size;
    const float* mean   = (const float*)d_in[0];
    const float* logvar = (const float*)d_in[1];
    const float* eps    = (const float*)d_in[2];
    const float* W0     = (const float*)d_in[3];
    const float* b0     = (const float*)d_in[4];
    const float* W1     = (const float*)d_in[5];
    const float* b1     = (const float*)d_in[6];
    const float* W2     = (const float*)d_in[7];
    const float* b2     = (const float*)d_in[8];
    float* out = (float*)d_out;

    cudaFuncSetAttribute(flow_kernel, cudaFuncAttributeMaxDynamicSharedMemorySize, SMEM_BYTES);
    flow_kernel<<<NBLK, TPB, SMEM_BYTES>>>(mean, logvar, eps, W0, b0, W1, b1, W2, b2, out);
}

// round 6
// speedup vs baseline: 1.1763x; 1.1763x over previous
#include <cuda_runtime.h>
#include <cstdint>

// Flow1: K=32, B=4096, ZS=128, ZH=64, HS=50, NF=2
#define KK   32
#define BB   4096
#define ZSv  128
#define ZHv  64
#define HSv  50
#define ROWS (KK*BB)          // 131072
#define TPB  128
#define MT   128              // rows per CTA
#define NBLK (ROWS/MT)        // 1024
#define ZMSTR 130             // z master row stride (floats)

// smem float-index offsets
#define ZM_OFF   0                       // z master [128][130] fp32 (both halves)
#define ZLO_OFF  (MT*ZMSTR)              // 16640: lo tile of SOURCE half [128][64]
#define H_OFF    (ZLO_OFF + MT*64)       // 24832: h tile (tf32-rna) [128][64]
#define W0HI_OFF (H_OFF + MT*64)         // 33024: W0 hi [64][64] (rows>=50 zero)
#define W0LO_OFF (W0HI_OFF + 4096)
#define W1HI_OFF (W0LO_OFF + 4096)       // W1 [64][64] (cols k>=50 zero)
#define W1LO_OFF (W1HI_OFF + 4096)
#define W2HI_OFF (W1LO_OFF + 4096)
#define W2LO_OFF (W2HI_OFF + 4096)
#define BIAS_OFF (W2LO_OFF + 4096)       // b0[64] b1[64] b2[64]
#define LG_OFF   (BIAS_OFF + 192)        // per-row logdet accum [128]
#define SMEM_FLOATS (LG_OFF + 128)       // 57920
#define SMEM_BYTES  (SMEM_FLOATS * 4)    // 231680 <= 232448 max
#define RP_OFF   W0HI_OFF                // rowpart [128][4] (prologue only; union)

__device__ __forceinline__ uint32_t tf32_rna_bits(float x) {
    uint32_t u; asm("cvt.rna.tf32.f32 %0, %1;" : "=r"(u) : "f"(x));
    return u;
}
__device__ __forceinline__ float truncm(float x) {       // tf32-truncate (mask low 13)
    return __uint_as_float(__float_as_uint(x) & 0xFFFFE000u);
}
__device__ __forceinline__ int idx8(int r, int c) {      // stride-64 swizzled tile index
    return r * 64 + (c ^ ((r & 7) << 2));
}
__device__ __forceinline__ void hmma(float (&d)[4],
                                     uint32_t a0, uint32_t a1, uint32_t a2, uint32_t a3,
                                     uint32_t b0, uint32_t b1) {
    asm volatile(
        "mma.sync.aligned.m16n8k8.row.col.f32.tf32.tf32.f32 "
        "{%0,%1,%2,%3}, {%4,%5,%6,%7}, {%8,%9}, {%0,%1,%2,%3};"
        : "+f"(d[0]), "+f"(d[1]), "+f"(d[2]), "+f"(d[3])
        : "r"(a0), "r"(a1), "r"(a2), "r"(a3), "r"(b0), "r"(b1));
}
// fragment map (m16n8k8 tf32):
//  A: a0=(g,t) a1=(g+8,t) a2=(g,t+4) a3=(g+8,t+4)   [row g = lane>>2, t = lane&3]
//  B: b0=(k=t,n=g) b1=(k=t+4,n=g)
//  D: d0=(g,2t) d1=(g,2t+1) d2=(g+8,2t) d3=(g+8,2t+1)

__device__ __forceinline__ float fast_tanh(float x) {
    float e = __expf(-2.f * fabsf(x));
    float t = __fdividef(1.f - e, 1.f + e);
    return copysignf(t, x);
}

__global__ void __launch_bounds__(TPB, 1) flow_mma(
    const float* __restrict__ mean, const float* __restrict__ logvar,
    const float* __restrict__ eps,
    const float* __restrict__ W0, const float* __restrict__ b0,
    const float* __restrict__ W1, const float* __restrict__ b1,
    const float* __restrict__ W2, const float* __restrict__ b2,
    float* __restrict__ out)
{
    extern __shared__ float sm[];
    float* ZM   = sm + ZM_OFF;
    float* ZLO  = sm + ZLO_OFF;
    float* H    = sm + H_OFF;
    float* b0sh = sm + BIAS_OFF;
    float* b1sh = b0sh + 64;
    float* b2sh = b1sh + 64;
    float* lgrow = sm + LG_OFF;
    float* rowpart = sm + RP_OFF;

    const int tid  = threadIdx.x;
    const int lane = tid & 31;
    const int warp = tid >> 5;
    const int g    = lane >> 2;      // groupID
    const int t    = lane & 3;       // threadID_in_group
    const int rA   = warp * 32 + g;  // mt0 base row for this thread
    const size_t r0    = (size_t)blockIdx.x * MT;
    const size_t bbase = (size_t)(r0 & (BB-1)) * ZSv;

    // ---------------- prologue: z = eps*exp(0.5*lv)+mean ; rowsum(lv+eps^2) ----
    #pragma unroll 4
    for (int j = 0; j < MT; j++) {
        size_t go = (size_t)j * ZSv + tid;
        float ep = eps[r0*ZSv + go];
        float lv = logvar[bbase + go];
        float mn = mean[bbase + go];
        float zv = fmaf(ep, __expf(0.5f*lv), mn);
        ZM[j*ZMSTR + tid] = zv;
        if (tid < 64)   // z1 = initial source half: build its lo tile
            ZLO[idx8(j, tid)] = __uint_as_float(tf32_rna_bits(zv - truncm(zv)));
        float c = fmaf(ep, ep, lv);
        #pragma unroll
        for (int o = 16; o; o >>= 1) c += __shfl_xor_sync(0xFFFFFFFFu, c, o);
        if (lane == 0) rowpart[j*4 + warp] = c;
    }
    __syncthreads();
    const float rsum = rowpart[tid*4+0] + rowpart[tid*4+1]
                     + rowpart[tid*4+2] + rowpart[tid*4+3];   // row = tid

    float lgr[4] = {0.f, 0.f, 0.f, 0.f};   // log2(1+e^-sr) sums for 4 owned rows

    // ---------------- 4 flow half-steps ---------------------------------------
    #pragma unroll 1
    for (int s = 0; s < 4; s++) {
        __syncthreads();   // prior step weight reads done; rsum read done (s=0)
        {   // stage weights hi/lo (tf32-compensated split), zero-padded
            const float* W0g = W0 + s*(HSv*ZHv);
            #pragma unroll 1
            for (int i = tid; i < 64*64; i += TPB) {
                int n = i >> 6, k = i & 63;
                float v = (n < HSv) ? W0g[n*ZHv + k] : 0.f;
                float hi = truncm(v);
                sm[W0HI_OFF + idx8(n, k)] = hi;
                sm[W0LO_OFF + idx8(n, k)] = __uint_as_float(tf32_rna_bits(v - hi));
            }
            const float* W1g = W1 + s*(ZHv*HSv);
            const float* W2g = W2 + s*(ZHv*HSv);
            #pragma unroll 1
            for (int i = tid; i < 64*64; i += TPB) {
                int n = i >> 6, k = i & 63;
                float v1 = (k < HSv) ? W1g[n*HSv + k] : 0.f;
                float v2 = (k < HSv) ? W2g[n*HSv + k] : 0.f;
                float h1 = truncm(v1), h2 = truncm(v2);
                int ix = idx8(n, k);
                sm[W1HI_OFF + ix] = h1;
                sm[W1LO_OFF + ix] = __uint_as_float(tf32_rna_bits(v1 - h1));
                sm[W2HI_OFF + ix] = h2;
                sm[W2LO_OFF + ix] = __uint_as_float(tf32_rna_bits(v2 - h2));
            }
            if (tid < 64) {
                b0sh[tid] = (tid < HSv) ? b0[s*HSv + tid] : 0.f;
                b1sh[tid] = b1[s*ZHv + tid];
                b2sh[tid] = b2[s*ZHv + tid];
            }
        }
        __syncthreads();

        const int srcoff = (s & 1) ? 64 : 0;
        const int tgtoff = 64 - srcoff;

        // ======== GEMM0: h = tanh(z_src @ W0^T + b0), error-compensated =======
        const uint32_t* w0hiU = (const uint32_t*)(sm + W0HI_OFF);
        const uint32_t* w0loU = (const uint32_t*)(sm + W0LO_OFF);
        const uint32_t* zloU  = (const uint32_t*)ZLO;
        const uint32_t* hU    = (const uint32_t*)H;

        #pragma unroll 1
        for (int nt = 0; nt < 8; nt += 2) {
            float acc[2][2][4];                   // [ntp][mt][4]
            #pragma unroll
            for (int i = 0; i < 2; i++)
                #pragma unroll
                for (int m = 0; m < 2; m++)
                    #pragma unroll
                    for (int v = 0; v < 4; v++) acc[i][m][v] = 0.f;

            #pragma unroll
            for (int kt = 0; kt < 8; kt++) {
                const int kz = kt*8 + t;
                const int kc = srcoff + kz;
                uint32_t am[2][4], zl[2][4];
                #pragma unroll
                for (int m = 0; m < 2; m++) {
                    const int rl = rA + 16*m, rh = rl + 8;
                    am[m][0] = __float_as_uint(ZM[rl*ZMSTR + kc])   & 0xFFFFE000u;
                    am[m][1] = __float_as_uint(ZM[rh*ZMSTR + kc])   & 0xFFFFE000u;
                    am[m][2] = __float_as_uint(ZM[rl*ZMSTR + kc+4]) & 0xFFFFE000u;
                    am[m][3] = __float_as_uint(ZM[rh*ZMSTR + kc+4]) & 0xFFFFE000u;
                    zl[m][0] = zloU[idx8(rl, kz)];
                    zl[m][1] = zloU[idx8(rh, kz)];
                    zl[m][2] = zloU[idx8(rl, kz+4)];
                    zl[m][3] = zloU[idx8(rh, kz+4)];
                }
                #pragma unroll
                for (int p = 0; p < 2; p++) {
                    const int n = (nt + p)*8 + g;
                    const uint32_t bh0 = w0hiU[idx8(n, kz)];
                    const uint32_t bh1 = w0hiU[idx8(n, kz+4)];
                    const uint32_t bl0 = w0loU[idx8(n, kz)];
                    const uint32_t bl1 = w0loU[idx8(n, kz+4)];
                    #pragma unroll
                    for (int m = 0; m < 2; m++) {
                        hmma(acc[p][m], am[m][0], am[m][1], am[m][2], am[m][3], bh0, bh1);
                        hmma(acc[p][m], am[m][0], am[m][1], am[m][2], am[m][3], bl0, bl1);
                        hmma(acc[p][m], zl[m][0], zl[m][1], zl[m][2], zl[m][3], bh0, bh1);
                    }
                }
            }
            // tanh epilogue -> H tile (rna tf32)
            #pragma unroll
            for (int p = 0; p < 2; p++) {
                const int cb = (nt + p)*8 + 2*t;
                #pragma unroll
                for (int m = 0; m < 2; m++) {
                    const int rl = rA + 16*m, rh = rl + 8;
                    float h00 = fast_tanh(acc[p][m][0] + b0sh[cb]);
                    float h01 = fast_tanh(acc[p][m][1] + b0sh[cb+1]);
                    float h10 = fast_tanh(acc[p][m][2] + b0sh[cb]);
                    float h11 = fast_tanh(acc[p][m][3] + b0sh[cb+1]);
                    // D layout: d0=(rl,cb) d1=(rl,cb+1) d2=(rh,cb) d3=(rh,cb+1)
                    float2 plo = make_float2(__uint_as_float(tf32_rna_bits(h00)),
                                             __uint_as_float(tf32_rna_bits(h01)));
                    float2 phi = make_float2(__uint_as_float(tf32_rna_bits(h10)),
                                             __uint_as_float(tf32_rna_bits(h11)));
                    *(float2*)(H + idx8(rl, cb)) = plo;
                    *(float2*)(H + idx8(rh, cb)) = phi;
                }
            }
        }
        __syncwarp();

        // ======== GEMM1/2: mew, sr ; update target half + logdet ==============
        const uint32_t* w1hiU = (const uint32_t*)(sm + W1HI_OFF);
        const uint32_t* w1loU = (const uint32_t*)(sm + W1LO_OFF);
        const uint32_t* w2hiU = (const uint32_t*)(sm + W2HI_OFF);
        const uint32_t* w2loU = (const uint32_t*)(sm + W2LO_OFF);

        #pragma unroll 1
        for (int nt = 0; nt < 8; nt++) {
            float am[2][4], av[2][4];
            #pragma unroll
            for (int m = 0; m < 2; m++)
                #pragma unroll
                for (int v = 0; v < 4; v++) { am[m][v] = 0.f; av[m][v] = 0.f; }

            #pragma unroll
            for (int kt = 0; kt < 8; kt++) {
                const int k0 = kt*8 + t;
                const int n  = nt*8 + g;
                const uint32_t c1h0 = w1hiU[idx8(n, k0)], c1h1 = w1hiU[idx8(n, k0+4)];
                const uint32_t c1l0 = w1loU[idx8(n, k0)], c1l1 = w1loU[idx8(n, k0+4)];
                const uint32_t c2h0 = w2hiU[idx8(n, k0)], c2h1 = w2hiU[idx8(n, k0+4)];
                const uint32_t c2l0 = w2loU[idx8(n, k0)], c2l1 = w2loU[idx8(n, k0+4)];
                #pragma unroll
                for (int m = 0; m < 2; m++) {
                    const int rl = rA + 16*m, rh = rl + 8;
                    const uint32_t a0 = hU[idx8(rl, k0)];
                    const uint32_t a1 = hU[idx8(rh, k0)];
                    const uint32_t a2 = hU[idx8(rl, k0+4)];
                    const uint32_t a3 = hU[idx8(rh, k0+4)];
                    hmma(am[m], a0, a1, a2, a3, c1h0, c1h1);
                    hmma(am[m], a0, a1, a2, a3, c1l0, c1l1);
                    hmma(av[m], a0, a1, a2, a3, c2h0, c2h1);
                    hmma(av[m], a0, a1, a2, a3, c2l0, c2l1);
                }
            }
            // update epilogue
            const int cb = nt*8 + 2*t;
            #pragma unroll
            for (int m = 0; m < 2; m++) {
                const int rl = rA + 16*m, rh = rl + 8;
                #pragma unroll
                for (int hh = 0; hh < 2; hh++) {
                    const int r = hh ? rh : rl;
                    const float mew0 = am[m][2*hh+0] + b1sh[cb];
                    const float mew1 = am[m][2*hh+1] + b1sh[cb+1];
                    const float sr0  = av[m][2*hh+0] + b2sh[cb];
                    const float sr1  = av[m][2*hh+1] + b2sh[cb+1];
                    const float e0 = __expf(-sr0), e1 = __expf(-sr1);
                    const float o0 = 1.f + e0,     o1 = 1.f + e1;
                    const float g0 = __fdividef(1.f, o0), g1 = __fdividef(1.f, o1);
                    float2 zo = *(const float2*)(ZM + r*ZMSTR + tgtoff + cb);
                    const float zn0 = fmaf(zo.x, g0, mew0);
                    const float zn1 = fmaf(zo.y, g1, mew1);
                    *(float2*)(ZM + r*ZMSTR + tgtoff + cb) = make_float2(zn0, zn1);
                    *(float2*)(ZLO + idx8(r, cb)) = make_float2(
                        __uint_as_float(tf32_rna_bits(zn0 - truncm(zn0))),
                        __uint_as_float(tf32_rna_bits(zn1 - truncm(zn1))));
                    lgr[m*2 + hh] += __log2f(o0) + __log2f(o1);
                }
            }
        }
    }

    // ---------------- logdet reduce + epilogue ---------------------------------
    #pragma unroll
    for (int i = 0; i < 4; i++) {
        float v = lgr[i];
        v += __shfl_xor_sync(0xFFFFFFFFu, v, 1);
        v += __shfl_xor_sync(0xFFFFFFFFu, v, 2);
        if (t == 0) lgrow[warp*32 + (i >> 1)*16 + (i & 1)*8 + g] = v;
    }
    __syncthreads();

    #pragma unroll 4
    for (int j = 0; j < MT; j++)
        out[(r0 + j)*ZSv + tid] = ZM[j*ZMSTR + tid];

    float logq = -0.5f * ((float)ZSv * 1.8378770664093453f + rsum);
    out[(size_t)ROWS*ZSv + r0 + tid] = logq + 0.69314718055994531f * lgrow[tid];
}

extern "C" void kernel_launch(void* const* d_in, const int* in_sizes, int n_in,
                              void* d_out, int out_size) {
    (void)in_sizes; (void)n_in; (void)out_size;
    const float* mean   = (const float*)d_in[0];
    const float* logvar = (const float*)d_in[1];
    const float* eps    = (const float*)d_in[2];
    const float* W0     = (const float*)d_in[3];
    const float* b0     = (const float*)d_in[4];
    const float* W1     = (const float*)d_in[5];
    const float* b1     = (const float*)d_in[6];
    const float* W2     = (const float*)d_in[7];
    const float* b2     = (const float*)d_in[8];
    float* out = (float*)d_out;

    cudaFuncSetAttribute(flow_mma, cudaFuncAttributeMaxDynamicSharedMemorySize, SMEM_BYTES);
    flow_mma<<<NBLK, TPB, SMEM_BYTES>>>(mean, logvar, eps, W0, b0, W1, b1, W2, b2, out);
}

// round 7
// speedup vs baseline: 2.0023x; 1.7022x over previous
#include <cuda_runtime.h>
#include <cstdint>

// Flow1: K=32, B=4096, ZS=128, ZH=64, HS=50, NF=2
#define KK   32
#define BB   4096
#define ZSv  128
#define ZHv  64
#define HSv  50
#define ROWS (KK*BB)          // 131072
#define TPB  256              // 8 warps: 4 M-stripes x 2 N-halves
#define MT   128              // rows per CTA
#define NBLK (ROWS/MT)        // 1024
#define ZMSTR 132             // z master stride: 4g+t conflict-free fragment loads

// smem float-index offsets
#define ZM_OFF   0                       // z master [128][132] fp32
#define ZLO_OFF  (MT*ZMSTR)              // source-half lo tile [128][64]
#define H_OFF    (ZLO_OFF + MT*64)       // h tile (tf32-rna) [128][64]
#define W0HI_OFF (H_OFF + MT*64)
#define W0LO_OFF (W0HI_OFF + 4096)
#define W1HI_OFF (W0LO_OFF + 4096)
#define W1LO_OFF (W1HI_OFF + 4096)
#define W2HI_OFF (W1LO_OFF + 4096)
#define W2LO_OFF (W2HI_OFF + 4096)
#define BIAS_OFF (W2LO_OFF + 4096)       // b0[64] b1[64] b2[64]
#define SMEM_FLOATS (BIAS_OFF + 192)     // 58048
#define SMEM_BYTES  (SMEM_FLOATS * 4)    // 232192 <= 232448
#define RP_OFF   W0HI_OFF                // rowpart [128][4] (prologue only)
#define LG_OFF   ZLO_OFF                 // lgpart [2][128] (epilogue only)

__device__ __forceinline__ uint32_t tf32_rna_bits(float x) {
    uint32_t u; asm("cvt.rna.tf32.f32 %0, %1;" : "=r"(u) : "f"(x));
    return u;
}
__device__ __forceinline__ float truncm(float x) {
    return __uint_as_float(__float_as_uint(x) & 0xFFFFE000u);
}
__device__ __forceinline__ float tanha(float x) {
    float y; asm("tanh.approx.f32 %0, %1;" : "=f"(y) : "f"(x));
    return y;
}
__device__ __forceinline__ int idx8(int r, int c) {
    return r * 64 + (c ^ ((r & 7) << 2));
}
__device__ __forceinline__ void hmma(float (&d)[4],
                                     uint32_t a0, uint32_t a1, uint32_t a2, uint32_t a3,
                                     uint32_t b0, uint32_t b1) {
    asm volatile(
        "mma.sync.aligned.m16n8k8.row.col.f32.tf32.tf32.f32 "
        "{%0,%1,%2,%3}, {%4,%5,%6,%7}, {%8,%9}, {%0,%1,%2,%3};"
        : "+f"(d[0]), "+f"(d[1]), "+f"(d[2]), "+f"(d[3])
        : "r"(a0), "r"(a1), "r"(a2), "r"(a3), "r"(b0), "r"(b1));
}

__global__ void __launch_bounds__(TPB, 1) flow_mma2(
    const float* __restrict__ mean, const float* __restrict__ logvar,
    const float* __restrict__ eps,
    const float* __restrict__ W0, const float* __restrict__ b0,
    const float* __restrict__ W1, const float* __restrict__ b1,
    const float* __restrict__ W2, const float* __restrict__ b2,
    float* __restrict__ out)
{
    extern __shared__ float sm[];
    float* ZM    = sm + ZM_OFF;
    float* ZLO   = sm + ZLO_OFF;
    float* H     = sm + H_OFF;
    float* b0sh  = sm + BIAS_OFF;
    float* b1sh  = b0sh + 64;
    float* b2sh  = b1sh + 64;
    float* rowpart = sm + RP_OFF;
    float* lgpart  = sm + LG_OFF;

    const int tid   = threadIdx.x;
    const int lane  = tid & 31;
    const int warp  = tid >> 5;
    const int warpM = warp & 3;        // M stripe (32 rows)
    const int nhalf = warp >> 2;       // N half
    const int g     = lane >> 2;
    const int t     = lane & 3;
    const int rA    = warpM * 32 + g;
    const int ntbase = nhalf * 4;
    const size_t r0    = (size_t)blockIdx.x * MT;
    const size_t bbase = (size_t)(r0 & (BB-1)) * ZSv;

    // ---------------- prologue: z = eps*exp(0.5*lv)+mean ; rowsum(lv+eps^2) ----
    #pragma unroll 4
    for (int it = 0; it < 64; it++) {
        int j   = it*2 + (tid >> 7);
        int col = tid & 127;
        size_t go = (size_t)j * ZSv + col;
        float ep = eps[r0*ZSv + go];
        float lv = logvar[bbase + go];
        float mn = mean[bbase + go];
        float zv = fmaf(ep, __expf(0.5f*lv), mn);
        ZM[j*ZMSTR + col] = zv;
        if (col < 64)    // z1 = first source half: build its lo tile
            ZLO[idx8(j, col)] = __uint_as_float(tf32_rna_bits(zv - truncm(zv)));
        float c = fmaf(ep, ep, lv);
        #pragma unroll
        for (int o = 16; o; o >>= 1) c += __shfl_xor_sync(0xFFFFFFFFu, c, o);
        if (lane == 0) rowpart[j*4 + ((tid >> 5) & 3)] = c;
    }
    __syncthreads();
    float rsum = 0.f;
    if (tid < 128)
        rsum = rowpart[tid*4+0] + rowpart[tid*4+1] + rowpart[tid*4+2] + rowpart[tid*4+3];

    float lgr[4] = {0.f, 0.f, 0.f, 0.f};

    const uint32_t* w0hiU = (const uint32_t*)(sm + W0HI_OFF);
    const uint32_t* w0loU = (const uint32_t*)(sm + W0LO_OFF);
    const uint32_t* w1hiU = (const uint32_t*)(sm + W1HI_OFF);
    const uint32_t* w1loU = (const uint32_t*)(sm + W1LO_OFF);
    const uint32_t* w2hiU = (const uint32_t*)(sm + W2HI_OFF);
    const uint32_t* w2loU = (const uint32_t*)(sm + W2LO_OFF);
    const uint32_t* zloU  = (const uint32_t*)ZLO;
    const uint32_t* hU    = (const uint32_t*)H;

    // ---------------- 4 flow half-steps ---------------------------------------
    #pragma unroll 1
    for (int s = 0; s < 4; s++) {
        __syncthreads();
        {   // stage weights hi/lo (tf32 split), zero-padded
            const float* W0g = W0 + s*(HSv*ZHv);
            #pragma unroll 1
            for (int i = tid; i < 64*64; i += TPB) {
                int n = i >> 6, k = i & 63;
                float v = (n < HSv) ? W0g[n*ZHv + k] : 0.f;
                float hi = truncm(v);
                int ix = idx8(n, k);
                sm[W0HI_OFF + ix] = hi;
                sm[W0LO_OFF + ix] = __uint_as_float(tf32_rna_bits(v - hi));
            }
            const float* W1g = W1 + s*(ZHv*HSv);
            const float* W2g = W2 + s*(ZHv*HSv);
            #pragma unroll 1
            for (int i = tid; i < 64*64; i += TPB) {
                int n = i >> 6, k = i & 63;
                float v1 = (k < HSv) ? W1g[n*HSv + k] : 0.f;
                float v2 = (k < HSv) ? W2g[n*HSv + k] : 0.f;
                float h1 = truncm(v1), h2 = truncm(v2);
                int ix = idx8(n, k);
                sm[W1HI_OFF + ix] = h1;
                sm[W1LO_OFF + ix] = __uint_as_float(tf32_rna_bits(v1 - h1));
                sm[W2HI_OFF + ix] = h2;
                sm[W2LO_OFF + ix] = __uint_as_float(tf32_rna_bits(v2 - h2));
            }
            if (tid < 64) {
                b0sh[tid] = (tid < HSv) ? b0[s*HSv + tid] : 0.f;
                b1sh[tid] = b1[s*ZHv + tid];
                b2sh[tid] = b2[s*ZHv + tid];
            }
        }
        __syncthreads();

        const int srcoff = (s & 1) ? 64 : 0;
        const int tgtoff = 64 - srcoff;

        // ======== GEMM0: h = tanh(z_src @ W0^T + b0), compensated ==============
        {
            float acc[4][2][4];
            #pragma unroll
            for (int nn = 0; nn < 4; nn++)
                #pragma unroll
                for (int m = 0; m < 2; m++)
                    #pragma unroll
                    for (int v = 0; v < 4; v++) acc[nn][m][v] = 0.f;

            #pragma unroll
            for (int kt = 0; kt < 8; kt++) {
                const int kz = kt*8 + t;
                const int kc = srcoff + kz;
                uint32_t am[2][4], zl[2][4];
                #pragma unroll
                for (int m = 0; m < 2; m++) {
                    const int rl = rA + 16*m, rh = rl + 8;
                    am[m][0] = __float_as_uint(ZM[rl*ZMSTR + kc])   & 0xFFFFE000u;
                    am[m][1] = __float_as_uint(ZM[rh*ZMSTR + kc])   & 0xFFFFE000u;
                    am[m][2] = __float_as_uint(ZM[rl*ZMSTR + kc+4]) & 0xFFFFE000u;
                    am[m][3] = __float_as_uint(ZM[rh*ZMSTR + kc+4]) & 0xFFFFE000u;
                    zl[m][0] = zloU[idx8(rl, kz)];
                    zl[m][1] = zloU[idx8(rh, kz)];
                    zl[m][2] = zloU[idx8(rl, kz+4)];
                    zl[m][3] = zloU[idx8(rh, kz+4)];
                }
                #pragma unroll
                for (int nn = 0; nn < 4; nn++) {
                    const int n = (ntbase + nn)*8 + g;
                    const uint32_t bh0 = w0hiU[idx8(n, kz)];
                    const uint32_t bh1 = w0hiU[idx8(n, kz+4)];
                    const uint32_t bl0 = w0loU[idx8(n, kz)];
                    const uint32_t bl1 = w0loU[idx8(n, kz+4)];
                    #pragma unroll
                    for (int m = 0; m < 2; m++) {
                        hmma(acc[nn][m], am[m][0], am[m][1], am[m][2], am[m][3], bh0, bh1);
                        hmma(acc[nn][m], am[m][0], am[m][1], am[m][2], am[m][3], bl0, bl1);
                        hmma(acc[nn][m], zl[m][0], zl[m][1], zl[m][2], zl[m][3], bh0, bh1);
                    }
                }
            }
            // tanh epilogue -> H (tf32-rna)
            #pragma unroll
            for (int nn = 0; nn < 4; nn++) {
                const int cb = (ntbase + nn)*8 + 2*t;
                #pragma unroll
                for (int m = 0; m < 2; m++) {
                    const int rl = rA + 16*m, rh = rl + 8;
                    float h00 = tanha(acc[nn][m][0] + b0sh[cb]);
                    float h01 = tanha(acc[nn][m][1] + b0sh[cb+1]);
                    float h10 = tanha(acc[nn][m][2] + b0sh[cb]);
                    float h11 = tanha(acc[nn][m][3] + b0sh[cb+1]);
                    *(float2*)(H + idx8(rl, cb)) = make_float2(
                        __uint_as_float(tf32_rna_bits(h00)),
                        __uint_as_float(tf32_rna_bits(h01)));
                    *(float2*)(H + idx8(rh, cb)) = make_float2(
                        __uint_as_float(tf32_rna_bits(h10)),
                        __uint_as_float(tf32_rna_bits(h11)));
                }
            }
        }
        __syncthreads();   // H complete (cross-warp consumption next)

        // ======== GEMM1/2: mew, sr ; update target half + logdet ===============
        #pragma unroll
        for (int grp = 0; grp < 2; grp++) {
            const int nt0 = ntbase + grp*2;
            float am2[2][2][4], av2[2][2][4];
            #pragma unroll
            for (int nn = 0; nn < 2; nn++)
                #pragma unroll
                for (int m = 0; m < 2; m++)
                    #pragma unroll
                    for (int v = 0; v < 4; v++) { am2[nn][m][v] = 0.f; av2[nn][m][v] = 0.f; }

            #pragma unroll
            for (int kt = 0; kt < 7; kt++) {      // k-tile 7 all-zero: skipped
                const int k0 = kt*8 + t;
                uint32_t hf[2][4];
                #pragma unroll
                for (int m = 0; m < 2; m++) {
                    const int rl = rA + 16*m, rh = rl + 8;
                    hf[m][0] = hU[idx8(rl, k0)];
                    hf[m][1] = hU[idx8(rh, k0)];
                    hf[m][2] = hU[idx8(rl, k0+4)];
                    hf[m][3] = hU[idx8(rh, k0+4)];
                }
                #pragma unroll
                for (int nn = 0; nn < 2; nn++) {
                    const int n = (nt0 + nn)*8 + g;
                    const uint32_t c1h0 = w1hiU[idx8(n, k0)], c1h1 = w1hiU[idx8(n, k0+4)];
                    const uint32_t c1l0 = w1loU[idx8(n, k0)], c1l1 = w1loU[idx8(n, k0+4)];
                    const uint32_t c2h0 = w2hiU[idx8(n, k0)], c2h1 = w2hiU[idx8(n, k0+4)];
                    const uint32_t c2l0 = w2loU[idx8(n, k0)], c2l1 = w2loU[idx8(n, k0+4)];
                    #pragma unroll
                    for (int m = 0; m < 2; m++) {
                        hmma(am2[nn][m], hf[m][0], hf[m][1], hf[m][2], hf[m][3], c1h0, c1h1);
                        hmma(am2[nn][m], hf[m][0], hf[m][1], hf[m][2], hf[m][3], c1l0, c1l1);
                        hmma(av2[nn][m], hf[m][0], hf[m][1], hf[m][2], hf[m][3], c2h0, c2h1);
                        hmma(av2[nn][m], hf[m][0], hf[m][1], hf[m][2], hf[m][3], c2l0, c2l1);
                    }
                }
            }
            // update epilogue
            #pragma unroll
            for (int nn = 0; nn < 2; nn++) {
                const int cb = (nt0 + nn)*8 + 2*t;
                #pragma unroll
                for (int m = 0; m < 2; m++) {
                    #pragma unroll
                    for (int hh = 0; hh < 2; hh++) {
                        const int r = rA + 16*m + 8*hh;
                        const float mew0 = am2[nn][m][2*hh+0] + b1sh[cb];
                        const float mew1 = am2[nn][m][2*hh+1] + b1sh[cb+1];
                        const float sr0  = av2[nn][m][2*hh+0] + b2sh[cb];
                        const float sr1  = av2[nn][m][2*hh+1] + b2sh[cb+1];
                        const float e0 = __expf(-sr0), e1 = __expf(-sr1);
                        const float o0 = 1.f + e0,     o1 = 1.f + e1;
                        const float g0 = __fdividef(1.f, o0);
                        const float g1 = __fdividef(1.f, o1);
                        lgr[m*2 + hh] += __log2f(o0) + __log2f(o1);
                        float2 zo = *(const float2*)(ZM + r*ZMSTR + tgtoff + cb);
                        const float zn0 = fmaf(zo.x, g0, mew0);
                        const float zn1 = fmaf(zo.y, g1, mew1);
                        *(float2*)(ZM + r*ZMSTR + tgtoff + cb) = make_float2(zn0, zn1);
                        *(float2*)(ZLO + idx8(r, cb)) = make_float2(
                            __uint_as_float(tf32_rna_bits(zn0 - truncm(zn0))),
                            __uint_as_float(tf32_rna_bits(zn1 - truncm(zn1))));
                    }
                }
            }
        }
    }

    // ---------------- logdet reduce (lgpart unions dead ZLO) --------------------
    __syncthreads();
    #pragma unroll
    for (int i = 0; i < 4; i++) {
        float v = lgr[i];
        v += __shfl_xor_sync(0xFFFFFFFFu, v, 1);
        v += __shfl_xor_sync(0xFFFFFFFFu, v, 2);
        if (t == 0)
            lgpart[nhalf*128 + warpM*32 + (i >> 1)*16 + (i & 1)*8 + g] = v;
    }
    __syncthreads();

    // ---------------- epilogue: z_out + logpz ----------------------------------
    #pragma unroll 4
    for (int it = 0; it < 64; it++) {
        int j   = it*2 + (tid >> 7);
        int col = tid & 127;
        out[(r0 + j)*ZSv + col] = ZM[j*ZMSTR + col];
    }
    if (tid < 128) {
        float lg = lgpart[tid] + lgpart[128 + tid];
        float logq = -0.5f * ((float)ZSv * 1.8378770664093453f + rsum);
        out[(size_t)ROWS*ZSv + r0 + tid] = logq + 0.69314718055994531f * lg;
    }
}

extern "C" void kernel_launch(void* const* d_in, const int* in_sizes, int n_in,
                              void* d_out, int out_size) {
    (void)in_sizes; (void)n_in; (void)out_size;
    const float* mean   = (const float*)d_in[0];
    const float* logvar = (const float*)d_in[1];
    const float* eps    = (const float*)d_in[2];
    const float* W0     = (const float*)d_in[3];
    const float* b0     = (const float*)d_in[4];
    const float* W1     = (const float*)d_in[5];
    const float* b1     = (const float*)d_in[6];
    const float* W2     = (const float*)d_in[7];
    const float* b2     = (const float*)d_in[8];
    float* out = (float*)d_out;

    cudaFuncSetAttribute(flow_mma2, cudaFuncAttributeMaxDynamicSharedMemorySize, SMEM_BYTES);
    flow_mma2<<<NBLK, TPB, SMEM_BYTES>>>(mean, logvar, eps, W0, b0, W1, b1, W2, b2, out);
}

// round 8
// speedup vs baseline: 2.5600x; 1.2785x over previous
#include <cuda_runtime.h>
#include <cstdint>

// Flow1: K=32, B=4096, ZS=128, ZH=64, HS=50, NF=2
#define KK   32
#define BB   4096
#define ZSv  128
#define ZHv  64
#define HSv  50
#define ROWS (KK*BB)          // 131072
#define TPB  512              // 16 warps: 8 M-stripes (16 rows) x 2 N-halves
#define MT   128              // rows per CTA
#define NBLK (ROWS/MT)        // 1024
#define ZMSTR 132             // z master stride

// smem float-index offsets
#define ZM_OFF   0                       // z master [128][132] fp32
#define ZLO_OFF  (MT*ZMSTR)              // source-half lo tile [128][64]
#define H_OFF    (ZLO_OFF + MT*64)       // h tile (tf32-rna) [128][64]
#define W0HI_OFF (H_OFF + MT*64)
#define W0LO_OFF (W0HI_OFF + 4096)
#define W1HI_OFF (W0LO_OFF + 4096)
#define W1LO_OFF (W1HI_OFF + 4096)
#define W2HI_OFF (W1LO_OFF + 4096)
#define W2LO_OFF (W2HI_OFF + 4096)
#define BIAS_OFF (W2LO_OFF + 4096)       // b0[64] b1[64] b2[64]
#define SMEM_FLOATS (BIAS_OFF + 192)     // 58048
#define SMEM_BYTES  (SMEM_FLOATS * 4)    // 232192 <= 232448
#define RP_OFF   W0HI_OFF                // rowpart [128][4] (prologue only)
#define LG_OFF   ZLO_OFF                 // lgpart [2][128] (epilogue only)

__device__ __forceinline__ uint32_t tf32_rna_bits(float x) {
    uint32_t u; asm("cvt.rna.tf32.f32 %0, %1;" : "=r"(u) : "f"(x));
    return u;
}
__device__ __forceinline__ float truncm(float x) {
    return __uint_as_float(__float_as_uint(x) & 0xFFFFE000u);
}
__device__ __forceinline__ float tanha(float x) {
    float y; asm("tanh.approx.f32 %0, %1;" : "=f"(y) : "f"(x));
    return y;
}
__device__ __forceinline__ int idx8(int r, int c) {
    return r * 64 + (c ^ ((r & 7) << 2));
}
__device__ __forceinline__ void hmma(float (&d)[4],
                                     uint32_t a0, uint32_t a1, uint32_t a2, uint32_t a3,
                                     uint32_t b0, uint32_t b1) {
    asm volatile(
        "mma.sync.aligned.m16n8k8.row.col.f32.tf32.tf32.f32 "
        "{%0,%1,%2,%3}, {%4,%5,%6,%7}, {%8,%9}, {%0,%1,%2,%3};"
        : "+f"(d[0]), "+f"(d[1]), "+f"(d[2]), "+f"(d[3])
        : "r"(a0), "r"(a1), "r"(a2), "r"(a3), "r"(b0), "r"(b1));
}

__global__ void __launch_bounds__(TPB, 1) flow_mma3(
    const float* __restrict__ mean, const float* __restrict__ logvar,
    const float* __restrict__ eps,
    const float* __restrict__ W0, const float* __restrict__ b0,
    const float* __restrict__ W1, const float* __restrict__ b1,
    const float* __restrict__ W2, const float* __restrict__ b2,
    float* __restrict__ out)
{
    extern __shared__ float sm[];
    float* ZM    = sm + ZM_OFF;
    float* ZLO   = sm + ZLO_OFF;
    float* H     = sm + H_OFF;
    float* b0sh  = sm + BIAS_OFF;
    float* b1sh  = b0sh + 64;
    float* b2sh  = b1sh + 64;
    float* rowpart = sm + RP_OFF;
    float* lgpart  = sm + LG_OFF;

    const int tid   = threadIdx.x;
    const int lane  = tid & 31;
    const int warp  = tid >> 5;
    const int warpM = warp & 7;        // M stripe (16 rows)
    const int nhalf = warp >> 3;       // N half
    const int g     = lane >> 2;
    const int t     = lane & 3;
    const int rl    = warpM * 16 + g;  // fragment rows rl, rl+8
    const int ntbase = nhalf * 4;
    const size_t r0    = (size_t)blockIdx.x * MT;
    const size_t bbase = (size_t)(r0 & (BB-1)) * ZSv;

    // ---------------- prologue: z = eps*exp(0.5*lv)+mean ; rowsum(lv+eps^2) ----
    #pragma unroll 4
    for (int it = 0; it < 32; it++) {
        int j   = it*4 + (tid >> 7);
        int col = tid & 127;
        size_t go = (size_t)j * ZSv + col;
        float ep = eps[r0*ZSv + go];
        float lv = logvar[bbase + go];
        float mn = mean[bbase + go];
        float zv = fmaf(ep, __expf(0.5f*lv), mn);
        ZM[j*ZMSTR + col] = zv;
        if (col < 64)    // z1 = first source half: build its lo tile
            ZLO[idx8(j, col)] = __uint_as_float(tf32_rna_bits(zv - truncm(zv)));
        float c = fmaf(ep, ep, lv);
        #pragma unroll
        for (int o = 16; o; o >>= 1) c += __shfl_xor_sync(0xFFFFFFFFu, c, o);
        if (lane == 0) rowpart[j*4 + ((tid >> 5) & 3)] = c;
    }
    __syncthreads();
    float rsum = 0.f;
    if (tid < 128)
        rsum = rowpart[tid*4+0] + rowpart[tid*4+1] + rowpart[tid*4+2] + rowpart[tid*4+3];

    float lgr[2] = {0.f, 0.f};

    const uint32_t* w0hiU = (const uint32_t*)(sm + W0HI_OFF);
    const uint32_t* w0loU = (const uint32_t*)(sm + W0LO_OFF);
    const uint32_t* w1hiU = (const uint32_t*)(sm + W1HI_OFF);
    const uint32_t* w1loU = (const uint32_t*)(sm + W1LO_OFF);
    const uint32_t* w2hiU = (const uint32_t*)(sm + W2HI_OFF);
    const uint32_t* w2loU = (const uint32_t*)(sm + W2LO_OFF);
    const uint32_t* zloU  = (const uint32_t*)ZLO;
    const uint32_t* hU    = (const uint32_t*)H;

    // ---------------- 4 flow half-steps ---------------------------------------
    #pragma unroll 1
    for (int s = 0; s < 4; s++) {
        __syncthreads();
        {   // stage weights hi/lo (tf32 split), zero-padded
            const float* W0g = W0 + s*(HSv*ZHv);
            #pragma unroll 1
            for (int i = tid; i < 64*64; i += TPB) {
                int n = i >> 6, k = i & 63;
                float v = (n < HSv) ? W0g[n*ZHv + k] : 0.f;
                float hi = truncm(v);
                int ix = idx8(n, k);
                sm[W0HI_OFF + ix] = hi;
                sm[W0LO_OFF + ix] = __uint_as_float(tf32_rna_bits(v - hi));
            }
            const float* W1g = W1 + s*(ZHv*HSv);
            const float* W2g = W2 + s*(ZHv*HSv);
            #pragma unroll 1
            for (int i = tid; i < 64*64; i += TPB) {
                int n = i >> 6, k = i & 63;
                float v1 = (k < HSv) ? W1g[n*HSv + k] : 0.f;
                float v2 = (k < HSv) ? W2g[n*HSv + k] : 0.f;
                float h1 = truncm(v1), h2 = truncm(v2);
                int ix = idx8(n, k);
                sm[W1HI_OFF + ix] = h1;
                sm[W1LO_OFF + ix] = __uint_as_float(tf32_rna_bits(v1 - h1));
                sm[W2HI_OFF + ix] = h2;
                sm[W2LO_OFF + ix] = __uint_as_float(tf32_rna_bits(v2 - h2));
            }
            if (tid < 64) {
                b0sh[tid] = (tid < HSv) ? b0[s*HSv + tid] : 0.f;
                b1sh[tid] = b1[s*ZHv + tid];
                b2sh[tid] = b2[s*ZHv + tid];
            }
        }
        __syncthreads();

        const int srcoff = (s & 1) ? 64 : 0;
        const int tgtoff = 64 - srcoff;

        // ======== GEMM0: h = tanh(z_src @ W0^T + b0), compensated ==============
        {
            float acc[4][4];
            #pragma unroll
            for (int nn = 0; nn < 4; nn++)
                #pragma unroll
                for (int v = 0; v < 4; v++) acc[nn][v] = 0.f;

            #pragma unroll
            for (int kt = 0; kt < 8; kt++) {
                const int kz = kt*8 + t;
                const int kc = srcoff + kz;
                const int rh = rl + 8;
                uint32_t am0 = __float_as_uint(ZM[rl*ZMSTR + kc])   & 0xFFFFE000u;
                uint32_t am1 = __float_as_uint(ZM[rh*ZMSTR + kc])   & 0xFFFFE000u;
                uint32_t am2 = __float_as_uint(ZM[rl*ZMSTR + kc+4]) & 0xFFFFE000u;
                uint32_t am3 = __float_as_uint(ZM[rh*ZMSTR + kc+4]) & 0xFFFFE000u;
                uint32_t zl0 = zloU[idx8(rl, kz)];
                uint32_t zl1 = zloU[idx8(rh, kz)];
                uint32_t zl2 = zloU[idx8(rl, kz+4)];
                uint32_t zl3 = zloU[idx8(rh, kz+4)];
                #pragma unroll
                for (int nn = 0; nn < 4; nn++) {
                    const int n = (ntbase + nn)*8 + g;
                    const uint32_t bh0 = w0hiU[idx8(n, kz)];
                    const uint32_t bh1 = w0hiU[idx8(n, kz+4)];
                    const uint32_t bl0 = w0loU[idx8(n, kz)];
                    const uint32_t bl1 = w0loU[idx8(n, kz+4)];
                    hmma(acc[nn], am0, am1, am2, am3, bh0, bh1);
                    hmma(acc[nn], am0, am1, am2, am3, bl0, bl1);
                    hmma(acc[nn], zl0, zl1, zl2, zl3, bh0, bh1);
                }
            }
            // tanh epilogue -> H (tf32-rna)
            #pragma unroll
            for (int nn = 0; nn < 4; nn++) {
                const int cb = (ntbase + nn)*8 + 2*t;
                const int rh = rl + 8;
                float h00 = tanha(acc[nn][0] + b0sh[cb]);
                float h01 = tanha(acc[nn][1] + b0sh[cb+1]);
                float h10 = tanha(acc[nn][2] + b0sh[cb]);
                float h11 = tanha(acc[nn][3] + b0sh[cb+1]);
                *(float2*)(H + idx8(rl, cb)) = make_float2(
                    __uint_as_float(tf32_rna_bits(h00)),
                    __uint_as_float(tf32_rna_bits(h01)));
                *(float2*)(H + idx8(rh, cb)) = make_float2(
                    __uint_as_float(tf32_rna_bits(h10)),
                    __uint_as_float(tf32_rna_bits(h11)));
            }
        }
        __syncthreads();   // H complete (cross-warp consumption next)

        // ======== GEMM1/2: mew, sr ; update target half + logdet ===============
        #pragma unroll
        for (int grp = 0; grp < 2; grp++) {
            const int nt0 = ntbase + grp*2;
            float am2a[2][4], av2a[2][4];
            #pragma unroll
            for (int nn = 0; nn < 2; nn++)
                #pragma unroll
                for (int v = 0; v < 4; v++) { am2a[nn][v] = 0.f; av2a[nn][v] = 0.f; }

            #pragma unroll
            for (int kt = 0; kt < 7; kt++) {      // k-tile 7 all-zero: skipped
                const int k0 = kt*8 + t;
                const int rh = rl + 8;
                const uint32_t hf0 = hU[idx8(rl, k0)];
                const uint32_t hf1 = hU[idx8(rh, k0)];
                const uint32_t hf2 = hU[idx8(rl, k0+4)];
                const uint32_t hf3 = hU[idx8(rh, k0+4)];
                #pragma unroll
                for (int nn = 0; nn < 2; nn++) {
                    const int n = (nt0 + nn)*8 + g;
                    const uint32_t c1h0 = w1hiU[idx8(n, k0)], c1h1 = w1hiU[idx8(n, k0+4)];
                    const uint32_t c1l0 = w1loU[idx8(n, k0)], c1l1 = w1loU[idx8(n, k0+4)];
                    const uint32_t c2h0 = w2hiU[idx8(n, k0)], c2h1 = w2hiU[idx8(n, k0+4)];
                    const uint32_t c2l0 = w2loU[idx8(n, k0)], c2l1 = w2loU[idx8(n, k0+4)];
                    hmma(am2a[nn], hf0, hf1, hf2, hf3, c1h0, c1h1);
                    hmma(am2a[nn], hf0, hf1, hf2, hf3, c1l0, c1l1);
                    hmma(av2a[nn], hf0, hf1, hf2, hf3, c2h0, c2h1);
                    hmma(av2a[nn], hf0, hf1, hf2, hf3, c2l0, c2l1);
                }
            }
            // update epilogue
            #pragma unroll
            for (int nn = 0; nn < 2; nn++) {
                const int cb = (nt0 + nn)*8 + 2*t;
                #pragma unroll
                for (int hh = 0; hh < 2; hh++) {
                    const int r = rl + 8*hh;
                    const float mew0 = am2a[nn][2*hh+0] + b1sh[cb];
                    const float mew1 = am2a[nn][2*hh+1] + b1sh[cb+1];
                    const float sr0  = av2a[nn][2*hh+0] + b2sh[cb];
                    const float sr1  = av2a[nn][2*hh+1] + b2sh[cb+1];
                    const float e0 = __expf(-sr0), e1 = __expf(-sr1);
                    const float o0 = 1.f + e0,     o1 = 1.f + e1;
                    const float g0 = __fdividef(1.f, o0);
                    const float g1 = __fdividef(1.f, o1);
                    lgr[hh] += __log2f(o0) + __log2f(o1);
                    float2 zo = *(const float2*)(ZM + r*ZMSTR + tgtoff + cb);
                    const float zn0 = fmaf(zo.x, g0, mew0);
                    const float zn1 = fmaf(zo.y, g1, mew1);
                    *(float2*)(ZM + r*ZMSTR + tgtoff + cb) = make_float2(zn0, zn1);
                    *(float2*)(ZLO + idx8(r, cb)) = make_float2(
                        __uint_as_float(tf32_rna_bits(zn0 - truncm(zn0))),
                        __uint_as_float(tf32_rna_bits(zn1 - truncm(zn1))));
                }
            }
        }
    }

    // ---------------- logdet reduce (lgpart unions dead ZLO) --------------------
    __syncthreads();
    #pragma unroll
    for (int i = 0; i < 2; i++) {
        float v = lgr[i];
        v += __shfl_xor_sync(0xFFFFFFFFu, v, 1);
        v += __shfl_xor_sync(0xFFFFFFFFu, v, 2);
        if (t == 0)
            lgpart[nhalf*128 + warpM*16 + i*8 + g] = v;
    }
    __syncthreads();

    // ---------------- epilogue: z_out + logpz ----------------------------------
    #pragma unroll 4
    for (int it = 0; it < 32; it++) {
        int j   = it*4 + (tid >> 7);
        int col = tid & 127;
        out[(r0 + j)*ZSv + col] = ZM[j*ZMSTR + col];
    }
    if (tid < 128) {
        float lg = lgpart[tid] + lgpart[128 + tid];
        float logq = -0.5f * ((float)ZSv * 1.8378770664093453f + rsum);
        out[(size_t)ROWS*ZSv + r0 + tid] = logq + 0.69314718055994531f * lg;
    }
}

extern "C" void kernel_launch(void* const* d_in, const int* in_sizes, int n_in,
                              void* d_out, int out_size) {
    (void)in_sizes; (void)n_in; (void)out_size;
    const float* mean   = (const float*)d_in[0];
    const float* logvar = (const float*)d_in[1];
    const float* eps    = (const float*)d_in[2];
    const float* W0     = (const float*)d_in[3];
    const float* b0     = (const float*)d_in[4];
    const float* W1     = (const float*)d_in[5];
    const float* b1     = (const float*)d_in[6];
    const float* W2     = (const float*)d_in[7];
    const float* b2     = (const float*)d_in[8];
    float* out = (float*)d_out;

    cudaFuncSetAttribute(flow_mma3, cudaFuncAttributeMaxDynamicSharedMemorySize, SMEM_BYTES);
    flow_mma3<<<NBLK, TPB, SMEM_BYTES>>>(mean, logvar, eps, W0, b0, W1, b1, W2, b2, out);
}

// round 9
// speedup vs baseline: 2.8261x; 1.1039x over previous
#include <cuda_runtime.h>
#include <cstdint>

// Flow1: K=32, B=4096, ZS=128, ZH=64, HS=50, NF=2
#define KK   32
#define BB   4096
#define ZSv  128
#define ZHv  64
#define HSv  50
#define ROWS (KK*BB)          // 131072
#define TPB  512              // 16 warps: 8 M-stripes (16 rows) x 2 N-halves
#define MT   128              // rows per CTA
#define NBLK (ROWS/MT)        // 1024
#define ZMSTR 132             // z master stride

// smem float-index offsets
#define ZM_OFF   0                       // z master [128][132] fp32
#define ZLO_OFF  (MT*ZMSTR)              // source-half lo tile [128][64]
#define H_OFF    (ZLO_OFF + MT*64)       // h tile (tf32-rna) [128][64]
#define W0HI_OFF (H_OFF + MT*64)         // W0 hi (trunc) [64][64]
#define W0LO_OFF (W0HI_OFF + 4096)       // W0 lo (rna resid)
#define W1T_OFF  (W0LO_OFF + 4096)       // W1 (rna tf32) [64][64]
#define W2T_OFF  (W1T_OFF + 4096)        // W2 (rna tf32)
#define BIAS_OFF (W2T_OFF + 4096)        // b0[64] b1[64] b2[64]
#define SMEM_FLOATS (BIAS_OFF + 192)     // 49856
#define SMEM_BYTES  (SMEM_FLOATS * 4)    // 199424
#define RP_OFF   W0HI_OFF                // rowpart [128][4] (prologue only)
#define LG_OFF   ZLO_OFF                 // lgpart [2][128] (epilogue only)

__device__ __forceinline__ uint32_t tf32_rna_bits(float x) {
    uint32_t u; asm("cvt.rna.tf32.f32 %0, %1;" : "=r"(u) : "f"(x));
    return u;
}
__device__ __forceinline__ float truncm(float x) {
    return __uint_as_float(__float_as_uint(x) & 0xFFFFE000u);
}
__device__ __forceinline__ float tanha(float x) {
    float y; asm("tanh.approx.f32 %0, %1;" : "=f"(y) : "f"(x));
    return y;
}
__device__ __forceinline__ int idx8(int r, int c) {
    return r * 64 + (c ^ ((r & 7) << 2));
}
__device__ __forceinline__ void hmma(float (&d)[4],
                                     uint32_t a0, uint32_t a1, uint32_t a2, uint32_t a3,
                                     uint32_t b0, uint32_t b1) {
    asm volatile(
        "mma.sync.aligned.m16n8k8.row.col.f32.tf32.tf32.f32 "
        "{%0,%1,%2,%3}, {%4,%5,%6,%7}, {%8,%9}, {%0,%1,%2,%3};"
        : "+f"(d[0]), "+f"(d[1]), "+f"(d[2]), "+f"(d[3])
        : "r"(a0), "r"(a1), "r"(a2), "r"(a3), "r"(b0), "r"(b1));
}

__global__ void __launch_bounds__(TPB, 1) flow_mma4(
    const float* __restrict__ mean, const float* __restrict__ logvar,
    const float* __restrict__ eps,
    const float* __restrict__ W0, const float* __restrict__ b0,
    const float* __restrict__ W1, const float* __restrict__ b1,
    const float* __restrict__ W2, const float* __restrict__ b2,
    float* __restrict__ out)
{
    extern __shared__ float sm[];
    float* ZM    = sm + ZM_OFF;
    float* ZLO   = sm + ZLO_OFF;
    float* H     = sm + H_OFF;
    float* b0sh  = sm + BIAS_OFF;
    float* b1sh  = b0sh + 64;
    float* b2sh  = b1sh + 64;
    float* rowpart = sm + RP_OFF;
    float* lgpart  = sm + LG_OFF;

    const int tid   = threadIdx.x;
    const int lane  = tid & 31;
    const int warp  = tid >> 5;
    const int warpM = warp & 7;        // M stripe (16 rows)
    const int nhalf = warp >> 3;       // N half
    const int g     = lane >> 2;
    const int t     = lane & 3;
    const int rl    = warpM * 16 + g;  // fragment rows rl, rl+8
    const int ntbase = nhalf * 4;
    const size_t r0    = (size_t)blockIdx.x * MT;
    const size_t bbase = (size_t)(r0 & (BB-1)) * ZSv;

    // ---------------- prologue: z = eps*exp(0.5*lv)+mean ; rowsum(lv+eps^2) ----
    #pragma unroll 4
    for (int it = 0; it < 32; it++) {
        int j   = it*4 + (tid >> 7);
        int col = tid & 127;
        size_t go = (size_t)j * ZSv + col;
        float ep = eps[r0*ZSv + go];
        float lv = logvar[bbase + go];
        float mn = mean[bbase + go];
        float zv = fmaf(ep, __expf(0.5f*lv), mn);
        ZM[j*ZMSTR + col] = zv;
        if (col < 64)    // z1 = first source half: build its lo tile
            ZLO[idx8(j, col)] = __uint_as_float(tf32_rna_bits(zv - truncm(zv)));
        float c = fmaf(ep, ep, lv);
        #pragma unroll
        for (int o = 16; o; o >>= 1) c += __shfl_xor_sync(0xFFFFFFFFu, c, o);
        if (lane == 0) rowpart[j*4 + ((tid >> 5) & 3)] = c;
    }
    __syncthreads();
    float rsum = 0.f;
    if (tid < 128)
        rsum = rowpart[tid*4+0] + rowpart[tid*4+1] + rowpart[tid*4+2] + rowpart[tid*4+3];

    float lgr[2] = {0.f, 0.f};

    const uint32_t* w0hiU = (const uint32_t*)(sm + W0HI_OFF);
    const uint32_t* w0loU = (const uint32_t*)(sm + W0LO_OFF);
    const uint32_t* w1tU  = (const uint32_t*)(sm + W1T_OFF);
    const uint32_t* w2tU  = (const uint32_t*)(sm + W2T_OFF);
    const uint32_t* zloU  = (const uint32_t*)ZLO;
    const uint32_t* hU    = (const uint32_t*)H;

    // ---------------- 4 flow half-steps ---------------------------------------
    #pragma unroll 1
    for (int s = 0; s < 4; s++) {
        __syncthreads();
        {   // stage weights (W0 hi/lo compensated, W1/W2 rna), zero-padded
            const float* W0g = W0 + s*(HSv*ZHv);
            #pragma unroll 1
            for (int i = tid; i < 64*64; i += TPB) {
                int n = i >> 6, k = i & 63;
                float v = (n < HSv) ? W0g[n*ZHv + k] : 0.f;
                float hi = truncm(v);
                int ix = idx8(n, k);
                sm[W0HI_OFF + ix] = hi;
                sm[W0LO_OFF + ix] = __uint_as_float(tf32_rna_bits(v - hi));
            }
            const float* W1g = W1 + s*(ZHv*HSv);
            const float* W2g = W2 + s*(ZHv*HSv);
            #pragma unroll 1
            for (int i = tid; i < 64*64; i += TPB) {
                int n = i >> 6, k = i & 63;
                float v1 = (k < HSv) ? W1g[n*HSv + k] : 0.f;
                float v2 = (k < HSv) ? W2g[n*HSv + k] : 0.f;
                int ix = idx8(n, k);
                sm[W1T_OFF + ix] = __uint_as_float(tf32_rna_bits(v1));
                sm[W2T_OFF + ix] = __uint_as_float(tf32_rna_bits(v2));
            }
            if (tid < 64) {
                b0sh[tid] = (tid < HSv) ? b0[s*HSv + tid] : 0.f;
                b1sh[tid] = b1[s*ZHv + tid];
                b2sh[tid] = b2[s*ZHv + tid];
            }
        }
        __syncthreads();

        const int srcoff = (s & 1) ? 64 : 0;
        const int tgtoff = 64 - srcoff;

        // ======== GEMM0: h = tanh(z_src @ W0^T + b0), compensated ==============
        // n-tile 7 (rows 56..63 of W0) is identically zero -> skipped, H zeroed.
        {
            float acc[4][4];
            #pragma unroll
            for (int nn = 0; nn < 4; nn++)
                #pragma unroll
                for (int v = 0; v < 4; v++) acc[nn][v] = 0.f;

            const int nlim = (nhalf == 1) ? 3 : 4;   // skip nt==7

            #pragma unroll
            for (int kt = 0; kt < 8; kt++) {
                const int kz = kt*8 + t;
                const int kc = srcoff + kz;
                const int rh = rl + 8;
                uint32_t am0 = __float_as_uint(ZM[rl*ZMSTR + kc])   & 0xFFFFE000u;
                uint32_t am1 = __float_as_uint(ZM[rh*ZMSTR + kc])   & 0xFFFFE000u;
                uint32_t am2 = __float_as_uint(ZM[rl*ZMSTR + kc+4]) & 0xFFFFE000u;
                uint32_t am3 = __float_as_uint(ZM[rh*ZMSTR + kc+4]) & 0xFFFFE000u;
                uint32_t zl0 = zloU[idx8(rl, kz)];
                uint32_t zl1 = zloU[idx8(rh, kz)];
                uint32_t zl2 = zloU[idx8(rl, kz+4)];
                uint32_t zl3 = zloU[idx8(rh, kz+4)];
                #pragma unroll
                for (int nn = 0; nn < 4; nn++) {
                    if (nn >= nlim) break;
                    const int n = (ntbase + nn)*8 + g;
                    const uint32_t bh0 = w0hiU[idx8(n, kz)];
                    const uint32_t bh1 = w0hiU[idx8(n, kz+4)];
                    const uint32_t bl0 = w0loU[idx8(n, kz)];
                    const uint32_t bl1 = w0loU[idx8(n, kz+4)];
                    hmma(acc[nn], am0, am1, am2, am3, bh0, bh1);
                    hmma(acc[nn], am0, am1, am2, am3, bl0, bl1);
                    hmma(acc[nn], zl0, zl1, zl2, zl3, bh0, bh1);
                }
            }
            // tanh epilogue -> H (tf32-rna); zero tile for nt==7
            #pragma unroll
            for (int nn = 0; nn < 4; nn++) {
                const int cb = (ntbase + nn)*8 + 2*t;
                const int rh = rl + 8;
                if (nn >= ((nhalf == 1) ? 3 : 4)) {
                    *(float2*)(H + idx8(rl, cb)) = make_float2(0.f, 0.f);
                    *(float2*)(H + idx8(rh, cb)) = make_float2(0.f, 0.f);
                } else {
                    float h00 = tanha(acc[nn][0] + b0sh[cb]);
                    float h01 = tanha(acc[nn][1] + b0sh[cb+1]);
                    float h10 = tanha(acc[nn][2] + b0sh[cb]);
                    float h11 = tanha(acc[nn][3] + b0sh[cb+1]);
                    *(float2*)(H + idx8(rl, cb)) = make_float2(
                        __uint_as_float(tf32_rna_bits(h00)),
                        __uint_as_float(tf32_rna_bits(h01)));
                    *(float2*)(H + idx8(rh, cb)) = make_float2(
                        __uint_as_float(tf32_rna_bits(h10)),
                        __uint_as_float(tf32_rna_bits(h11)));
                }
            }
        }
        __syncthreads();   // H complete (cross-warp consumption next)

        // ======== GEMM1/2: mew, sr ; update target half + logdet ===============
        #pragma unroll
        for (int grp = 0; grp < 2; grp++) {
            const int nt0 = ntbase + grp*2;
            float am2a[2][4], av2a[2][4];
            #pragma unroll
            for (int nn = 0; nn < 2; nn++)
                #pragma unroll
                for (int v = 0; v < 4; v++) { am2a[nn][v] = 0.f; av2a[nn][v] = 0.f; }

            #pragma unroll
            for (int kt = 0; kt < 7; kt++) {      // k-tile 7 all-zero: skipped
                const int k0 = kt*8 + t;
                const int rh = rl + 8;
                const uint32_t hf0 = hU[idx8(rl, k0)];
                const uint32_t hf1 = hU[idx8(rh, k0)];
                const uint32_t hf2 = hU[idx8(rl, k0+4)];
                const uint32_t hf3 = hU[idx8(rh, k0+4)];
                #pragma unroll
                for (int nn = 0; nn < 2; nn++) {
                    const int n = (nt0 + nn)*8 + g;
                    const uint32_t c1h0 = w1tU[idx8(n, k0)], c1h1 = w1tU[idx8(n, k0+4)];
                    const uint32_t c2h0 = w2tU[idx8(n, k0)], c2h1 = w2tU[idx8(n, k0+4)];
                    hmma(am2a[nn], hf0, hf1, hf2, hf3, c1h0, c1h1);
                    hmma(av2a[nn], hf0, hf1, hf2, hf3, c2h0, c2h1);
                }
            }
            // update epilogue
            #pragma unroll
            for (int nn = 0; nn < 2; nn++) {
                const int cb = (nt0 + nn)*8 + 2*t;
                #pragma unroll
                for (int hh = 0; hh < 2; hh++) {
                    const int r = rl + 8*hh;
                    const float mew0 = am2a[nn][2*hh+0] + b1sh[cb];
                    const float mew1 = am2a[nn][2*hh+1] + b1sh[cb+1];
                    const float sr0  = av2a[nn][2*hh+0] + b2sh[cb];
                    const float sr1  = av2a[nn][2*hh+1] + b2sh[cb+1];
                    const float e0 = __expf(-sr0), e1 = __expf(-sr1);
                    const float o0 = 1.f + e0,     o1 = 1.f + e1;
                    const float g0 = __fdividef(1.f, o0);
                    const float g1 = __fdividef(1.f, o1);
                    lgr[hh] += __log2f(o0) + __log2f(o1);
                    float2 zo = *(const float2*)(ZM + r*ZMSTR + tgtoff + cb);
                    const float zn0 = fmaf(zo.x, g0, mew0);
                    const float zn1 = fmaf(zo.y, g1, mew1);
                    *(float2*)(ZM + r*ZMSTR + tgtoff + cb) = make_float2(zn0, zn1);
                    *(float2*)(ZLO + idx8(r, cb)) = make_float2(
                        __uint_as_float(tf32_rna_bits(zn0 - truncm(zn0))),
                        __uint_as_float(tf32_rna_bits(zn1 - truncm(zn1))));
                }
            }
        }
    }

    // ---------------- logdet reduce (lgpart unions dead ZLO) --------------------
    __syncthreads();
    #pragma unroll
    for (int i = 0; i < 2; i++) {
        float v = lgr[i];
        v += __shfl_xor_sync(0xFFFFFFFFu, v, 1);
        v += __shfl_xor_sync(0xFFFFFFFFu, v, 2);
        if (t == 0)
            lgpart[nhalf*128 + warpM*16 + i*8 + g] = v;
    }
    __syncthreads();

    // ---------------- epilogue: z_out + logpz ----------------------------------
    #pragma unroll 4
    for (int it = 0; it < 32; it++) {
        int j   = it*4 + (tid >> 7);
        int col = tid & 127;
        out[(r0 + j)*ZSv + col] = ZM[j*ZMSTR + col];
    }
    if (tid < 128) {
        float lg = lgpart[tid] + lgpart[128 + tid];
        float logq = -0.5f * ((float)ZSv * 1.8378770664093453f + rsum);
        out[(size_t)ROWS*ZSv + r0 + tid] = logq + 0.69314718055994531f * lg;
    }
}

extern "C" void kernel_launch(void* const* d_in, const int* in_sizes, int n_in,
                              void* d_out, int out_size) {
    (void)in_sizes; (void)n_in; (void)out_size;
    const float* mean   = (const float*)d_in[0];
    const float* logvar = (const float*)d_in[1];
    const float* eps    = (const float*)d_in[2];
    const float* W0     = (const float*)d_in[3];
    const float* b0     = (const float*)d_in[4];
    const float* W1     = (const float*)d_in[5];
    const float* b1     = (const float*)d_in[6];
    const float* W2     = (const float*)d_in[7];
    const float* b2     = (const float*)d_in[8];
    float* out = (float*)d_out;

    cudaFuncSetAttribute(flow_mma4, cudaFuncAttributeMaxDynamicSharedMemorySize, SMEM_BYTES);
    flow_mma4<<<NBLK, TPB, SMEM_BYTES>>>(mean, logvar, eps, W0, b0, W1, b1, W2, b2, out);
}